// round 6
// baseline (speedup 1.0000x reference)
#include <cuda_runtime.h>
#include <cstdint>

// Forward 5/3 lifting wavelet, 2D separable, fully streaming: no smem, no barriers.
// x: (8, 32, 512, 512) f32 -> out: (8, 128, 256, 256) f32
// out channels: [LL(0:32) | LH(32:64) | HL(64:96) | HH(96:128)]
//
//   d[i] = odd[i] - 0.5*(even[il] + even[ir]), il=(i==0)?1:i-1, ir=(i==255)?254:i+1
//   s[i] = even[i] + 0.25*(d[il] + d[ir])     (same reflected indices)
//
// Warp owns a 32-column x 32-row coefficient tile and streams down rows with a
// 3-deep sliding window; all shuffles are warp-uniform (selection via selects).

static constexpr unsigned FULL = 0xffffffffu;

struct SD { float s, d; };

__global__ __launch_bounds__(256)
void lwt53_stream_kernel(const float* __restrict__ x, float* __restrict__ out) {
    const int lane   = threadIdx.x & 31;
    const int warp   = threadIdx.x >> 5;
    const int blk    = blockIdx.x;
    const int colblk = blk & 7;          // 8 column blocks x 32 coefficients
    const int bc     = blk >> 3;         // image index
    const int C0     = colblk * 32;
    const int k0     = warp * 32;        // first output coefficient row

    const float* __restrict__ xim = x + (size_t)bc * (512 * 512);

    const bool leftEdge  = (C0 == 0);
    const bool rightEdge = (C0 == 224);
    const bool haloL = (lane == 0)  && !leftEdge;
    const bool haloR = (lane == 31) && !rightEdge;

    // Row lifting of input row m; returns (s,d) at coefficient column C0+lane.
    // All shuffles executed by all lanes unconditionally.
    auto rowlift = [&](int m) -> SD {
        const float* __restrict__ row = xim + (size_t)m * 512;
        const float2 p = reinterpret_cast<const float2*>(row)[C0 + lane];
        float4 hl = make_float4(0.f, 0.f, 0.f, 0.f);
        float4 hr = make_float4(0.f, 0.f, 0.f, 0.f);
        if (haloL) hl = *reinterpret_cast<const float4*>(row + 2 * C0 - 4);
        if (haloR) hr = *reinterpret_cast<const float4*>(row + 2 * C0 + 64);
        const float ev = p.x, od = p.y;

        const float up_e  = __shfl_up_sync(FULL, ev, 1);
        const float dn_e  = __shfl_down_sync(FULL, ev, 1);
        const float b1_e  = __shfl_sync(FULL, ev, 1);
        const float b30_e = __shfl_sync(FULL, ev, 30);
        // i=0: il=1 -> b1_e ; natural dn_e already == even[1] for ir.
        // i=255: ir=254 -> b30_e ; natural up_e already == even[254] for il.
        const float evL = (lane == 0)  ? (leftEdge  ? b1_e  : hl.z) : up_e;
        const float evR = (lane == 31) ? (rightEdge ? b30_e : hr.x) : dn_e;
        const float d = od - 0.5f * (evL + evR);

        // halo d values (meaningful only on interior-edge lanes 0 / 31)
        const float dhl = hl.w - 0.5f * (hl.x + ev);   // d[C0-1]
        const float dhr = hr.y - 0.5f * (ev + hr.z);   // d[C0+32]

        const float up_d = __shfl_up_sync(FULL, d, 1);
        const float dn_d = __shfl_down_sync(FULL, d, 1);
        const float b1_d = __shfl_sync(FULL, d, 1);
        const float dL = (lane == 0)  ? (leftEdge  ? b1_d : dhl) : up_d;
        const float dR = (lane == 31) ? (rightEdge ? up_d : dhr) : dn_d;

        SD r;
        r.d = d;
        r.s = ev + 0.25f * (dL + dR);
        return r;
    };

    // Output pointers
    const int b = bc >> 5;
    const int c = bc & 31;
    float* __restrict__ base = out + ((size_t)b * 128 + c) * 65536;
    float* __restrict__ oLL = base;
    float* __restrict__ oLH = base + 32 * 65536;
    float* __restrict__ oHL = base + 64 * 65536;
    float* __restrict__ oHH = base + 96 * 65536;
    const int col = C0 + lane;

    // ---- column-lifting sliding window ----
    // E[j] = rowlift(2j), O[j] = rowlift(2j+1)
    // D[j] = O[j] - 0.5*(E[j-1] + E[j+1])
    // S[j] = E[j] + 0.25*(D[j-1] + D[j+1])
    const int jstart = (k0 == 0)   ? 0   : (k0 - 1);
    const int jend   = (k0 == 224) ? 255 : (k0 + 32);

    SD eA = rowlift(2 * ((k0 == 0) ? 1 : (k0 - 2)));  // E[refl(jstart-1)]
    SD eB = rowlift(2 * jstart);                      // E[jstart]

    float Dm1s = 0.f, Dm2s = 0.f, Dm1t = 0.f, Dm2t = 0.f;

    for (int j = jstart; j <= jend; ++j) {
        const int jp = (j >= 255) ? 254 : (j + 1);    // refl E[256] -> E[254]
        const SD eC = rowlift(2 * jp);
        const SD O  = rowlift(2 * j + 1);

        const float Ds = O.s - 0.5f * (eA.s + eC.s);
        const float Dt = O.d - 0.5f * (eA.d + eC.d);

        if (j >= k0 && j <= k0 + 31) {
            const size_t o = (size_t)j * 256 + col;
            __stcs(oLH + o, Ds);
            __stcs(oHH + o, Dt);
        }
        if (j >= k0 + 1) {
            // S[j-1]; at the global top, S[0] uses D[1] on both sides
            const float DAs = (k0 == 0 && j == 1) ? Ds : Dm2s;
            const float DAt = (k0 == 0 && j == 1) ? Dt : Dm2t;
            const float Ss = eA.s + 0.25f * (DAs + Ds);
            const float St = eA.d + 0.25f * (DAt + Dt);
            const size_t o = (size_t)(j - 1) * 256 + col;
            __stcs(oLL + o, Ss);
            __stcs(oHL + o, St);
        }

        Dm2s = Dm1s; Dm1s = Ds;
        Dm2t = Dm1t; Dm1t = Dt;
        eA = eB; eB = eC;
    }

    if (k0 == 224) {
        // S[255] = E[255] + 0.25*(D[254] + D[254]); after final shift:
        // eA = E[255], Dm2 = D[254]
        const float Ss = eA.s + 0.25f * (Dm2s + Dm2s);
        const float St = eA.d + 0.25f * (Dm2t + Dm2t);
        const size_t o = (size_t)255 * 256 + col;
        __stcs(oLL + o, Ss);
        __stcs(oHL + o, St);
    }
}

extern "C" void kernel_launch(void* const* d_in, const int* in_sizes, int n_in,
                              void* d_out, int out_size) {
    const float* x = (const float*)d_in[0];
    float* out = (float*)d_out;
    (void)in_sizes; (void)n_in; (void)out_size;

    dim3 grid(256 * 8);   // (image, colblk)
    dim3 block(256);      // 8 warps = 8 row-chunks of one column block
    lwt53_stream_kernel<<<grid, block>>>(x, out);
}

// round 7
// speedup vs baseline: 1.6995x; 1.6995x over previous
#include <cuda_runtime.h>
#include <cstdint>

// Forward 5/3 lifting wavelet, 2D separable, fused tile kernel.
// x: (8, 32, 512, 512) f32 -> out: (8, 128, 256, 256) f32
// out channels: [LL(0:32) | LH(32:64) | HL(64:96) | HH(96:128)]
//
//   d[i] = odd[i] - 0.5*(even[il] + even[ir]), il=(i==0)?1:i-1, ir=(i==255)?254:i+1
//   s[i] = even[i] + 0.25*(d[il] + d[ir])     (same reflected indices)
//
// R=8 output rows per strip, 256-thread CTAs, 47KB smem -> 4 CTAs/SM:
// four independent load->barrier->store machines per SM keep DRAM reads and
// writes continuously interleaved (fix for the bursty 2-CTA phase structure).

static constexpr int H = 512;
static constexpr int Wd = 512;
static constexpr int R = 8;               // output rows per strip
static constexpr int NSTRIP = 256 / R;    // 32
static constexpr int NBC = 8 * 32;        // 256 images
static constexpr int MAXROWS = 2 * R + 7; // 23
static constexpr int SMEM_BYTES = MAXROWS * Wd * 4; // 47104

static constexpr unsigned FULL = 0xffffffffu;

__device__ __forceinline__ float2 f2_add(float2 a, float2 b) {
    return make_float2(a.x + b.x, a.y + b.y);
}
__device__ __forceinline__ float2 f2_fma(float k, float2 a, float2 b) {
    return make_float2(fmaf(k, a.x, b.x), fmaf(k, a.y, b.y));
}

__global__ __launch_bounds__(256, 4)
void lwt53_fused_kernel(const float* __restrict__ x, float* __restrict__ out) {
    extern __shared__ float A[];   // [nrows][512]; per row: s in [0,256), d in [256,512)

    const int blk   = blockIdx.x;
    const int strip = blk & (NSTRIP - 1);
    const int bc    = blk >> 5;            // log2(NSTRIP)=5
    const int r0    = strip * R;

    const int mlo   = max(0, 2 * r0 - 4);
    const int mhi   = min(H - 1, 2 * r0 + 2 * R + 2);
    const int nrows = mhi - mlo + 1;

    const float* __restrict__ xim = x + (size_t)bc * (H * Wd) + (size_t)mlo * Wd;

    const int tid  = threadIdx.x;
    const int warp = tid >> 5;
    const int lane = tid & 31;

    // ================= Phase A: row lifting in registers =================
    // Warp handles whole rows. Lane l owns pairs (64j+2l, 64j+2l+1), j=0..3 —
    // one coalesced float4 load each.
    for (int r = warp; r < nrows; r += 8) {
        const float4* __restrict__ xr =
            reinterpret_cast<const float4*>(xim + (size_t)r * Wd);
        float eA[4], oA[4], eB[4], oB[4];
        #pragma unroll
        for (int j = 0; j < 4; j++) {
            const float4 v = xr[32 * j + lane];
            eA[j] = v.x; oA[j] = v.y; eB[j] = v.z; oB[j] = v.w;
        }

        float dA[4], dB[4];
        #pragma unroll
        for (int j = 0; j < 4; j++) {
            float up = __shfl_up_sync(FULL, eB[j], 1);
            float cp = __shfl_sync(FULL, (j > 0) ? eB[j - 1] : eB[j], 31);
            float Eprev = (lane == 0) ? ((j == 0) ? eB[0] : cp) : up;   // refl i=0
            float dn = __shfl_down_sync(FULL, eA[j], 1);
            float cn = __shfl_sync(FULL, (j < 3) ? eA[j + 1] : eA[j], 0);
            float Enext = (lane == 31) ? ((j == 3) ? eA[3] : cn) : dn;  // refl i=255
            dA[j] = oA[j] - 0.5f * (Eprev + eB[j]);
            dB[j] = oB[j] - 0.5f * (eA[j] + Enext);
        }

        float* Arow = A + r * Wd;
        float2* __restrict__ srow = reinterpret_cast<float2*>(Arow);
        float2* __restrict__ drow = reinterpret_cast<float2*>(Arow + 256);
        #pragma unroll
        for (int j = 0; j < 4; j++) {
            float up = __shfl_up_sync(FULL, dB[j], 1);
            float cp = __shfl_sync(FULL, (j > 0) ? dB[j - 1] : dB[j], 31);
            float Dprev = (lane == 0) ? ((j == 0) ? dB[0] : cp) : up;
            float dn = __shfl_down_sync(FULL, dA[j], 1);
            float cn = __shfl_sync(FULL, (j < 3) ? dA[j + 1] : dA[j], 0);
            float Dnext = (lane == 31) ? ((j == 3) ? dA[3] : cn) : dn;
            float sA = eA[j] + 0.25f * (Dprev + dB[j]);
            float sB = eB[j] + 0.25f * (dA[j] + Dnext);
            srow[32 * j + lane] = make_float2(sA, sB);
            drow[32 * j + lane] = make_float2(dA[j], dB[j]);
        }
    }
    __syncthreads();

    // ============ Phase B: column lifting, 3-term sliding window ============
    // Thread owns a float2 column pair. t<128: s-columns (-> LL/LH);
    // t>=128: d-columns (-> HL/HH). Recurrence identical to the verified R6
    // streaming loop, reading smem rows instead of lifting gmem rows.
    {
        const int t  = tid;
        const int cc = (t & 127) * 2;                   // coefficient column (even)
        const int sb = (t < 128) ? 0 : 256;             // smem half offset

        auto ldrow = [&](int j) -> float2 {             // E[j] column pair
            return *reinterpret_cast<const float2*>(
                A + (2 * j - mlo) * Wd + sb + cc);
        };
        auto ldodd = [&](int j) -> float2 {             // O[j] column pair
            return *reinterpret_cast<const float2*>(
                A + (2 * j + 1 - mlo) * Wd + sb + cc);
        };

        const int b = bc >> 5;
        const int c = bc & 31;
        float* __restrict__ base = out + ((size_t)b * 128 + c) * 65536;
        float* __restrict__ sOut = base + ((t < 128) ? (size_t)0 : 64 * 65536);
        float* __restrict__ dOut = base + ((t < 128) ? 32 * 65536 : 96 * 65536);

        const int jstart = (r0 == 0)   ? 0   : (r0 - 1);
        const int jend   = (r0 == 248) ? 255 : (r0 + R);

        float2 eA = ldrow((r0 == 0) ? 1 : (r0 - 2));    // E[refl(jstart-1)]
        float2 eB = ldrow(jstart);                      // E[jstart]
        float2 Dm1 = make_float2(0.f, 0.f), Dm2 = make_float2(0.f, 0.f);

        for (int j = jstart; j <= jend; ++j) {
            const int jp = (j >= 255) ? 254 : (j + 1);
            const float2 eC = ldrow(jp);
            const float2 O  = ldodd(j);

            const float2 D = f2_fma(-0.5f, f2_add(eA, eC), O);

            if (j >= r0 && j <= r0 + R - 1) {
                __stcs(reinterpret_cast<float2*>(dOut + (size_t)j * 256 + cc), D);
            }
            if (j >= r0 + 1) {
                const float2 DA = (r0 == 0 && j == 1) ? D : Dm2;  // S[0] reflect
                const float2 S = f2_fma(0.25f, f2_add(DA, D), eA);
                __stcs(reinterpret_cast<float2*>(sOut + (size_t)(j - 1) * 256 + cc), S);
            }

            Dm2 = Dm1; Dm1 = D;
            eA = eB; eB = eC;
        }

        if (r0 == 248) {
            // S[255] = E[255] + 0.25*(D[254] + D[254]); after final shift eA=E[255], Dm2=D[254]
            const float2 S = f2_fma(0.5f, Dm2, eA);
            __stcs(reinterpret_cast<float2*>(sOut + (size_t)255 * 256 + cc), S);
        }
    }
}

extern "C" void kernel_launch(void* const* d_in, const int* in_sizes, int n_in,
                              void* d_out, int out_size) {
    const float* x = (const float*)d_in[0];
    float* out = (float*)d_out;
    (void)in_sizes; (void)n_in; (void)out_size;

    static bool attr_set = false;
    if (!attr_set) {
        cudaFuncSetAttribute(lwt53_fused_kernel,
                             cudaFuncAttributeMaxDynamicSharedMemorySize, SMEM_BYTES);
        attr_set = true;
    }

    dim3 grid(NBC * NSTRIP);   // 8192
    dim3 block(256);
    lwt53_fused_kernel<<<grid, block, SMEM_BYTES>>>(x, out);
}